// round 15
// baseline (speedup 1.0000x reference)
#include <cuda_runtime.h>
#include <cuda_bf16.h>
#include <cstdint>

// Problem constants
#define BC      16            // B*C = 8*2
#define LL      2048
#define TSZ     17
#define PAD     8
#define KPAD    16            // MMA covers taps 0..15; tap 16 exact in fp32
#define TM      256           // CTA m-tile

// tf32 plane of xf (taps 0..15): [bc][l][16]
__device__ float g_xf_hi[BC * LL * KPAD];
__device__ float g_xf16[BC * LL];          // tap 16, full fp32

__device__ __forceinline__ float to_tf32(float v) {
    uint32_t b;
    asm("cvt.rna.tf32.f32 %0, %1;" : "=r"(b) : "f"(v));
    return __uint_as_float(b);
}

// m16n8k8 tf32 MMA (sm_80+ baseline; valid on plain sm_103 target)
__device__ __forceinline__ void mma_tf32(float* c,
                                         uint32_t a0, uint32_t a1, uint32_t a2, uint32_t a3,
                                         uint32_t b0, uint32_t b1) {
    asm volatile(
        "mma.sync.aligned.m16n8k8.row.col.f32.tf32.tf32.f32 "
        "{%0,%1,%2,%3}, {%4,%5,%6,%7}, {%8,%9}, {%0,%1,%2,%3};"
        : "+f"(c[0]), "+f"(c[1]), "+f"(c[2]), "+f"(c[3])
        : "r"(a0), "r"(a1), "r"(a2), "r"(a3), "r"(b0), "r"(b1));
}

// ============ Kernel 0: xf build, 4 threads per l-row ============
__global__ void build_xf_kernel(const float* __restrict__ x,
                                const float* __restrict__ filt) {
    __shared__ float sf[TSZ * TSZ];
    __shared__ float sxw[80];

    const int tid = threadIdx.x;
    const int gid = blockIdx.x * 256 + tid;
    const int tq  = gid & 3;
    const int row = gid >> 2;             // bc*LL + l
    const int bc  = row >> 11;
    const int c   = bc & 1;
    const int lr  = row & 63;
    const int blk_l0 = (row & 2047) - lr;

    for (int i = tid; i < TSZ * TSZ; i += 256)
        sf[i] = filt[c * TSZ * TSZ + i];
    if (tid < 80) {
        int gi = blk_l0 + tid - PAD;
        sxw[tid] = (gi >= 0 && gi < LL) ? x[bc * LL + gi] : 0.0f;
    }
    __syncthreads();

    const int t0 = tq * 4;
    float a4[4] = {0.0f, 0.0f, 0.0f, 0.0f};
    float a16 = 0.0f;
#pragma unroll
    for (int s = 0; s < TSZ; s++) {
        float xv = sxw[lr + s];
        const float* fr = &sf[s * TSZ + t0];
        a4[0] += xv * fr[0];
        a4[1] += xv * fr[1];
        a4[2] += xv * fr[2];
        a4[3] += xv * fr[3];
        if (tq == 0) a16 += xv * sf[s * TSZ + 16];
    }

    reinterpret_cast<float4*>(g_xf_hi)[row * 4 + tq] =
        make_float4(to_tf32(a4[0]), to_tf32(a4[1]), to_tf32(a4[2]), to_tf32(a4[3]));
    if (tq == 0) g_xf16[row] = a16;
}

// ============ Kernel 1: 2-pass split-B tf32 GEMM, 128(l) x 256(m) CTA tile ============
// D = Ah[128,16]*(Bh+Bl)[16,256] + xf16[l]*x[m+8] (fp32)
// 8 warps: wy(4,l) x wx(2,m); warp covers 32(l) x 128(m) as FOUR sequential
// 32x32 halves (acc 32 regs live) -> ~80 regs -> 3 CTAs/SM.
// B fragments come from precomputed float2 pair arrays: wpair[i] = (w[i], w[i+4]).
#define ASTRIDE 20            // A smem row stride (conflict-free fragment reads)
#define SSTRIDE 40            // stage row stride (conflict-free STS.64 + LDS.128)

__global__ void __launch_bounds__(256, 3)
filter_mma_kernel(const float* __restrict__ x, float* __restrict__ out) {
    __shared__ float  pool[4608];         // As[2560] (until af hoist); stage after
    __shared__ float  win_f[288];         // fp32 window (280 used, zero-padded)
    __shared__ float2 wpair_h[272];       // (tf32hi[i], tf32hi[i+4])
    __shared__ float2 wpair_l[272];       // (tf32lo[i], tf32lo[i+4])
    __shared__ float  sxf16[128];

    float* As = pool;

    const int tid = threadIdx.x;
    const int wid = tid >> 5;
    const int lane = tid & 31;
    const int g   = lane >> 2;    // 0..7
    const int tig = lane & 3;     // 0..3
    const int wy = wid >> 1;      // 0..3  (l)
    const int wx = wid & 1;       // 0..1  (m)

    const int bc = blockIdx.z;
    const int l0 = blockIdx.y * 128;
    const int m0 = blockIdx.x * TM;

    // ---- fp32 window fill: win_f[i] = x[bc][m0 + i - 8], i in [0,280) ----
    for (int i = tid; i < 288; i += 256) {
        int gi = m0 + i - PAD;
        win_f[i] = (i < 280 && gi >= 0 && gi < LL) ? x[bc * LL + gi] : 0.0f;
    }
    if (tid < 128)
        sxf16[tid] = g_xf16[bc * LL + l0 + tid];

    // ---- A fill: [128][16] gmem -> smem stride 20, float4 ----
    {
        const float4* gh = reinterpret_cast<const float4*>(g_xf_hi) + (size_t)(bc * LL + l0) * 4;
#pragma unroll
        for (int it = 0; it < 2; it++) {
            int f4 = it * 256 + tid;          // 0..511
            int row = f4 >> 2, q = f4 & 3;
            *reinterpret_cast<float4*>(&As[row * ASTRIDE + q * 4]) = gh[f4];
        }
    }
    __syncthreads();

    // ---- B pair arrays (reads win_f; valid after sync) ----
    for (int i = tid; i < 272; i += 256) {
        float v0 = win_f[i], v1 = win_f[i + 4];
        float h0 = to_tf32(v0), h1 = to_tf32(v1);
        wpair_h[i] = make_float2(h0, h1);
        wpair_l[i] = make_float2(to_tf32(v0 - h0), to_tf32(v1 - h1));
    }

    const int rbase = wy * 32 + g;            // A fragment row base (local l)

    // ---- A fragments hoisted ONCE (shared by all passes and halves) ----
    uint32_t af[2][2][4];                     // [kt][mf][a0..a3]
#pragma unroll
    for (int kt = 0; kt < 2; kt++) {
        const int kb = kt * 8 + tig;
#pragma unroll
        for (int mf = 0; mf < 2; mf++) {
            const float* ar = As + (rbase + mf * 16) * ASTRIDE + kb;
            af[kt][mf][0] = __float_as_uint(ar[0]);
            af[kt][mf][1] = __float_as_uint(ar[8 * ASTRIDE]);
            af[kt][mf][2] = __float_as_uint(ar[4]);
            af[kt][mf][3] = __float_as_uint(ar[8 * ASTRIDE + 4]);
        }
    }
    __syncthreads();                      // As reads done; pool becomes stage; pairs visible

    float* stg = pool + wid * (8 * SSTRIDE);   // 320 floats per warp
    const int r4 = lane >> 3;             // 0..3
    const int c8 = lane & 7;              // 0..7

    float a16[2][2];
#pragma unroll
    for (int mf = 0; mf < 2; mf++) {
        a16[mf][0] = sxf16[rbase + mf * 16];
        a16[mf][1] = sxf16[rbase + mf * 16 + 8];
    }

    // ================== four sequential 32-col halves ==================
#pragma unroll 1
    for (int half = 0; half < 4; half++) {
        const int mh = wx * 128 + half * 32;  // m offset within CTA tile
        const int wbase = mh + g + tig;       // B pair-gather base

        float acc[2][4][4];
#pragma unroll
        for (int mf = 0; mf < 2; mf++)
#pragma unroll
            for (int nf = 0; nf < 4; nf++)
#pragma unroll
                for (int j = 0; j < 4; j++) acc[mf][nf][j] = 0.0f;

#pragma unroll
        for (int p = 0; p < 2; p++) {
            const float2* wp = (p == 0) ? wpair_h : wpair_l;
            float2 bp[5];                     // bp[q] = (b0,b1) for q = nf+kt
#pragma unroll
            for (int q = 0; q < 5; q++) bp[q] = wp[wbase + 8 * q];
#pragma unroll
            for (int kt = 0; kt < 2; kt++) {
#pragma unroll
                for (int mf = 0; mf < 2; mf++) {
#pragma unroll
                    for (int nf = 0; nf < 4; nf++)
                        mma_tf32(acc[mf][nf],
                                 af[kt][mf][0], af[kt][mf][1], af[kt][mf][2], af[kt][mf][3],
                                 __float_as_uint(bp[nf + kt].x),
                                 __float_as_uint(bp[nf + kt].y));
                }
            }
        }

        // ---- exact tap-16 rank-1 update (fma pipe) ----
#pragma unroll
        for (int nf = 0; nf < 4; nf++) {
            int cb = mh + nf * 8 + 2 * tig + 16;
            float bf0 = win_f[cb];
            float bf1 = win_f[cb + 1];
#pragma unroll
            for (int mf = 0; mf < 2; mf++) {
                acc[mf][nf][0] += a16[mf][0] * bf0;
                acc[mf][nf][1] += a16[mf][0] * bf1;
                acc[mf][nf][2] += a16[mf][1] * bf0;
                acc[mf][nf][3] += a16[mf][1] * bf1;
            }
        }

        // ---- staged epilogue: per-warp smem transpose -> coalesced STG.128 ----
        const int colg = m0 + mh + c8 * 4;
#pragma unroll
        for (int mf = 0; mf < 2; mf++) {
#pragma unroll
            for (int h = 0; h < 2; h++) {
#pragma unroll
                for (int nf = 0; nf < 4; nf++)
                    *reinterpret_cast<float2*>(&stg[g * SSTRIDE + nf * 8 + 2 * tig]) =
                        make_float2(acc[mf][nf][2 * h], acc[mf][nf][2 * h + 1]);
                __syncwarp();
                const int rowbase = l0 + wy * 32 + mf * 16 + 8 * h;
#pragma unroll
                for (int i = 0; i < 2; i++) {
                    int rr = r4 + 4 * i;
                    float4 v = *reinterpret_cast<const float4*>(&stg[rr * SSTRIDE + c8 * 4]);
                    *reinterpret_cast<float4*>(
                        out + (size_t)(bc * LL + rowbase + rr) * LL + colg) = v;
                }
                __syncwarp();
            }
        }
    }
}

extern "C" void kernel_launch(void* const* d_in, const int* in_sizes, int n_in,
                              void* d_out, int out_size) {
    const float* x    = (const float*)d_in[0];   // [8,2,2048]
    const float* filt = (const float*)d_in[1];   // [1,2,17,17]
    float* out = (float*)d_out;                  // [8,2,2048,2048]

    build_xf_kernel<<<(BC * LL * 4) / 256, 256>>>(x, filt);

    dim3 grid(LL / TM, LL / 128, BC);
    filter_mma_kernel<<<grid, 256>>>(x, out);
}